// round 14
// baseline (speedup 1.0000x reference)
#include <cuda_runtime.h>
#include <cuda_fp16.h>
#include <cstdint>

#define Dd 1024
#define Bb 32
#define Ss 2048
#define Mtot (Bb * Ss)          // 65536
#define M_TILE 128
#define N_TILE 128
#define K_TILE 64               // fp16 elems per stage
#define NSTG 3
#define NTILES (Dd / N_TILE)    // 8
#define NCHUNK (Dd / K_TILE)    // 16
#define TOT_TILES (NTILES * (Mtot / M_TILE))   // 4096

#define ROW_BYTES 144           // 64 fp16 = 128B data + 16B pad (conflict-free)

#define OFF_BAR  0              // full[0..2] at +0,8,16 ; empty[0..2] at +24,32,40
#define OFF_EP   1024           // 128*4 floats = 2 KB epilogue scratch
#define STAGE_BYTES (M_TILE * ROW_BYTES + N_TILE * ROW_BYTES)   // 36864
#define OFF_A(s) (3072 + (s) * STAGE_BYTES)
#define OFF_B(s) (OFF_A(s) + M_TILE * ROW_BYTES)
#define SMEM_BYTES (3072 + NSTG * STAGE_BYTES)                   // 113664

// fused prep kernel block ranges
#define ECONV_BLOCKS 16384
#define WCONV_BLOCKS 1024
#define PREP_BLOCKS  1024

__device__ float g_Hq[Bb * Dd];
__device__ __half g_Ehf[(size_t)Mtot * Dd];   // 128 MB
__device__ __half g_WhfT[Dd * Dd];            // 2 MB, [n][k]
__device__ float g_partial[NTILES * Mtot];    // 2 MB

__device__ __forceinline__ float tanh_fast(float x) {
    float y; asm("tanh.approx.f32 %0, %1;" : "=f"(y) : "f"(x)); return y;
}
__device__ __forceinline__ uint32_t pack_f16x2(float lo, float hi) {
    __half2 h = __floats2half2_rn(lo, hi);
    return *reinterpret_cast<uint32_t*>(&h);
}
__device__ __forceinline__ void mma_f16(float (&d)[4], const uint32_t (&a)[4],
                                        const uint32_t (&b)[2]) {
    asm volatile(
        "mma.sync.aligned.m16n8k16.row.col.f32.f16.f16.f32 "
        "{%0,%1,%2,%3}, {%4,%5,%6,%7}, {%8,%9}, {%0,%1,%2,%3};"
        : "+f"(d[0]), "+f"(d[1]), "+f"(d[2]), "+f"(d[3])
        : "r"(a[0]), "r"(a[1]), "r"(a[2]), "r"(a[3]), "r"(b[0]), "r"(b[1]));
}
__device__ __forceinline__ void ldmatrix_x4(uint32_t& r0, uint32_t& r1,
                                            uint32_t& r2, uint32_t& r3,
                                            uint32_t addr) {
    asm volatile("ldmatrix.sync.aligned.m8n8.x4.shared.b16 {%0,%1,%2,%3}, [%4];"
                 : "=r"(r0), "=r"(r1), "=r"(r2), "=r"(r3) : "r"(addr));
}
__device__ __forceinline__ void cp_async16(uint32_t dst, const void* src) {
    asm volatile("cp.async.cg.shared.global [%0], [%1], 16;"
                 :: "r"(dst), "l"(src) : "memory");
}
__device__ __forceinline__ uint32_t smem_u32(const void* p) {
    uint32_t a;
    asm("{ .reg .u64 t; cvta.to.shared.u64 t, %1; cvt.u32.u64 %0, t; }"
        : "=r"(a) : "l"(p));
    return a;
}

// ---- mbarrier primitives (sm_80+ portable subset) ----
#define MBARRIER_INIT(mbar, cnt) \
    asm volatile("mbarrier.init.shared.b64 [%0], %1;" \
        :: "r"((uint32_t)(mbar)), "r"((uint32_t)(cnt)) : "memory")
#define MBARRIER_ARRIVE(mbar) \
    asm volatile("mbarrier.arrive.shared.b64 _, [%0];" \
        :: "r"((uint32_t)(mbar)) : "memory")
#define CP_ASYNC_MBAR_ARRIVE(mbar) \
    asm volatile("cp.async.mbarrier.arrive.noinc.shared.b64 [%0];" \
        :: "r"((uint32_t)(mbar)) : "memory")

#define MBARRIER_WAIT_PARITY(mbar, parity) do { \
    uint32_t _m = (uint32_t)(mbar); uint32_t _p = (uint32_t)(parity); uint32_t _d; \
    asm volatile("{\n\t.reg .pred p;\n\t" \
        "mbarrier.try_wait.parity.shared.b64 p, [%1], %2;\n\t" \
        "selp.b32 %0, 1, 0, p;\n\t}" : "=r"(_d) : "r"(_m), "r"(_p) : "memory"); \
    if (!_d) { \
        asm volatile("{\n\t.reg .pred P1;\n\t" \
            "WL_%=:\n\t" \
            "mbarrier.try_wait.parity.shared.b64 P1, [%0], %1;\n\t" \
            "@P1 bra.uni WD_%=;\n\t" \
            "bra.uni WL_%=;\n\t" \
            "WD_%=:\n\t}" :: "r"(_m), "r"(_p) : "memory"); \
    } } while (0)

// ---------------------------------------------------------------------------
// Kernel 0 (fused prep): econv | wconvT | prep, partitioned by blockIdx.x.
// ---------------------------------------------------------------------------
__global__ void fused_prep_kernel(const float* __restrict__ E,
                                  const float* __restrict__ W,
                                  const float* __restrict__ hidden,
                                  const float* __restrict__ bias) {
    const int bid = blockIdx.x;
    const int t = threadIdx.x;

    if (bid < ECONV_BLOCKS) {
        const size_t i = ((size_t)bid * 256 + t) * 16;
#pragma unroll
        for (int q = 0; q < 2; q++) {
            float4 x0 = __ldg(reinterpret_cast<const float4*>(E + i + q * 8));
            float4 x1 = __ldg(reinterpret_cast<const float4*>(E + i + q * 8 + 4));
            uint4 o;
            o.x = pack_f16x2(x0.x, x0.y);
            o.y = pack_f16x2(x0.z, x0.w);
            o.z = pack_f16x2(x1.x, x1.y);
            o.w = pack_f16x2(x1.z, x1.w);
            __stcs(reinterpret_cast<uint4*>(&g_Ehf[i + q * 8]), o);
        }
    } else if (bid < ECONV_BLOCKS + WCONV_BLOCKS) {
        __shared__ float tile[32][33];
        const int id = bid - ECONV_BLOCKS;
        const float* Wb = W + (size_t)Dd * Dd;
        const int kt = (id & 31) * 32;
        const int nt = (id >> 5) * 32;
        const int tx = t & 31, ty = t >> 5;
#pragma unroll
        for (int i = 0; i < 4; i++)
            tile[ty + 8 * i][tx] = Wb[(size_t)(kt + ty + 8 * i) * Dd + nt + tx];
        __syncthreads();
#pragma unroll
        for (int i = 0; i < 4; i++)
            g_WhfT[(size_t)(nt + ty + 8 * i) * Dd + kt + tx] =
                __float2half_rn(tile[tx][ty + 8 * i]);
    } else {
        __shared__ float h[Dd];
        __shared__ float red[256];
        const int id = bid - ECONV_BLOCKS - WCONV_BLOCKS;
        const int n0 = (id & 31) * 32;
        const int b = id >> 5;
        {
            float4 v4 = *reinterpret_cast<const float4*>(hidden + b * Dd + t * 4);
            h[t * 4 + 0] = v4.x; h[t * 4 + 1] = v4.y;
            h[t * 4 + 2] = v4.z; h[t * 4 + 3] = v4.w;
        }
        __syncthreads();
        const int n = n0 + (t & 31);
        const int kbeg = (t >> 5) * 128;
        float acc = 0.f;
#pragma unroll 8
        for (int k = kbeg; k < kbeg + 128; k++)
            acc = fmaf(h[k], W[(size_t)k * Dd + n], acc);
        red[t] = acc;
        __syncthreads();
        if (t < 32) {
            float s = bias[n0 + t];
#pragma unroll
            for (int j = 0; j < 8; j++) s += red[j * 32 + t];
            g_Hq[b * Dd + n0 + t] = s;
        }
    }
}

// ---------------------------------------------------------------------------
// Kernel 2: persistent fp16 GEMM, mbarrier pipeline flowing ACROSS tiles.
// 8 warps of 64x32, 2 CTA/SM. grid = 2 * num_SMs, block 256
// ---------------------------------------------------------------------------
__global__ __launch_bounds__(256, 2)
void gemm_tanh_kernel(const float* __restrict__ v, int step) {
    extern __shared__ __align__(1024) char smem[];
    const uint32_t sb = smem_u32(smem);

    const int tid = threadIdx.x;
    const int wid = tid >> 5;
    const int lane = tid & 31;
    const int g = lane >> 2;
    const int tig = lane & 3;
    const int warp_m = wid & 1;        // 2 warps along M (64 rows each)
    const int warp_n = wid >> 1;       // 4 warps along N (32 cols each)
    const int bid = blockIdx.x;

    const uint32_t FULL  = sb + OFF_BAR;        // +8*s
    const uint32_t EMPTY = sb + OFF_BAR + 24;   // +8*s

    if (tid == 0) {
#pragma unroll
        for (int s = 0; s < NSTG; s++) {
            MBARRIER_INIT(FULL + 8 * s, 256);   // one completion-arrive per thread
            MBARRIER_INIT(EMPTY + 8 * s, 8);    // one arrive per warp
        }
    }
    __syncthreads();   // mbarrier init visible

    const int my_tiles = (TOT_TILES - bid + step - 1) / step;
    if (my_tiles <= 0) return;
    const int total_chunks = my_tiles * NCHUNK;

    uint32_t aoff[4], boff[2];
#pragma unroll
    for (int mf = 0; mf < 4; mf++) {
        int row = warp_m * 64 + mf * 16 + (lane & 7) + ((lane >> 3) & 1) * 8;
        aoff[mf] = row * ROW_BYTES + ((lane >> 4) & 1) * 16;
    }
#pragma unroll
    for (int np = 0; np < 2; np++) {
        int row = warp_n * 32 + np * 16 + (lane & 7) + ((lane >> 4) & 1) * 8;
        boff[np] = row * ROW_BYTES + ((lane >> 3) & 1) * 16;
    }

    // issue copies for GLOBAL chunk j (tile = bid + step*(j/16), chunk j%16)
    auto issue_stage = [&](int j) {
        const int t = bid + step * (j >> 4);
        const int m0 = (t >> 3) << 7;
        const int n0 = (t & 7) << 7;
        const int kt = (j & 15) * K_TILE;
        const int s = j % NSTG;
        const uint32_t abase = sb + OFF_A(s);
        const uint32_t bbase = sb + OFF_B(s);
#pragma unroll
        for (int p = 0; p < 4; p++) {
            int id = tid + p * 256;               // 0..1023
            int row = id >> 3, ch = id & 7;
            cp_async16(abase + row * ROW_BYTES + ch * 16,
                       &g_Ehf[(size_t)(m0 + row) * Dd + kt + ch * 8]);
        }
#pragma unroll
        for (int p = 0; p < 4; p++) {
            int id = tid + p * 256;
            int row = id >> 3, ch = id & 7;
            cp_async16(bbase + row * ROW_BYTES + ch * 16,
                       &g_WhfT[(size_t)(n0 + row) * Dd + kt + ch * 8]);
        }
        CP_ASYNC_MBAR_ARRIVE(FULL + 8 * s);       // signal on completion
    };

    issue_stage(0);
    if (total_chunks > 1) issue_stage(1);

    float* ep = reinterpret_cast<float*>(smem + OFF_EP);   // 128 x 4 floats

    for (int ti = 0; ti < my_tiles; ti++) {
        const int t = bid + step * ti;
        const int m0 = (t >> 3) << 7;
        const int n0 = (t & 7) << 7;
        const int b = m0 >> 11;

        float acc[4][4][4];
#pragma unroll
        for (int mf = 0; mf < 4; mf++)
#pragma unroll
            for (int nf = 0; nf < 4; nf++)
#pragma unroll
                for (int i = 0; i < 4; i++) acc[mf][nf][i] = 0.f;

#pragma unroll 1
        for (int i = 0; i < NCHUNK; i++) {
            const int gch = ti * NCHUNK + i;
            const int s = gch % NSTG;
            MBARRIER_WAIT_PARITY(FULL + 8 * s, (gch / NSTG) & 1);

            const uint32_t As = sb + OFF_A(s);
            const uint32_t Bs = sb + OFF_B(s);
#pragma unroll
            for (int kk = 0; kk < 4; kk++) {          // 4 x k16 steps
                const int kb = kk * 32;
                uint32_t afrag[4][4], bfrag[4][2];
#pragma unroll
                for (int mf = 0; mf < 4; mf++)
                    ldmatrix_x4(afrag[mf][0], afrag[mf][1],
                                afrag[mf][2], afrag[mf][3],
                                As + aoff[mf] + kb);
#pragma unroll
                for (int np = 0; np < 2; np++)
                    ldmatrix_x4(bfrag[2 * np][0], bfrag[2 * np][1],
                                bfrag[2 * np + 1][0], bfrag[2 * np + 1][1],
                                Bs + boff[np] + kb);
#pragma unroll
                for (int mf = 0; mf < 4; mf++)
#pragma unroll
                    for (int nf = 0; nf < 4; nf++)
                        mma_f16(acc[mf][nf], afrag[mf], bfrag[nf]);
            }
            if (lane == 0) MBARRIER_ARRIVE(EMPTY + 8 * s);

            // producer: refill with chunk gch+2 (possibly next tile's chunk)
            const int j = gch + 2;
            if (j < total_chunks) {
                const int s2 = j % NSTG;
                if (j >= NSTG)
                    MBARRIER_WAIT_PARITY(EMPTY + 8 * s2, ((j / NSTG) - 1) & 1);
                issue_stage(j);
            }
        }

        // ---- epilogue (next tile's stages already streaming in) ----
        float psum[8];
#pragma unroll
        for (int r = 0; r < 8; r++) psum[r] = 0.f;
#pragma unroll
        for (int nf = 0; nf < 4; nf++)
#pragma unroll
            for (int j = 0; j < 2; j++) {
                const int c = n0 + warp_n * 32 + nf * 8 + 2 * tig + j;
                const float hq = __ldg(&g_Hq[b * Dd + c]);
                const float vv = __ldg(&v[c]);
#pragma unroll
                for (int mf = 0; mf < 4; mf++) {
#pragma unroll
                    for (int half = 0; half < 2; half++) {
                        float e = tanh_fast(acc[mf][nf][half * 2 + j] + hq);
                        psum[mf * 2 + half] = fmaf(e, vv, psum[mf * 2 + half]);
                    }
                }
            }
#pragma unroll
        for (int r = 0; r < 8; r++) {
            psum[r] += __shfl_xor_sync(0xffffffffu, psum[r], 1);
            psum[r] += __shfl_xor_sync(0xffffffffu, psum[r], 2);
        }
        if (tig == 0) {
#pragma unroll
            for (int r = 0; r < 8; r++) {
                const int mf = r >> 1, half = r & 1;
                const int lrow = warp_m * 64 + mf * 16 + half * 8 + g;
                ep[lrow * 4 + warp_n] = psum[r];
            }
        }
        __syncthreads();
        if (tid < M_TILE) {
            float sum = ep[tid * 4] + ep[tid * 4 + 1] +
                        ep[tid * 4 + 2] + ep[tid * 4 + 3];
            g_partial[(size_t)(n0 >> 7) * Mtot + m0 + tid] = sum;
        }
        __syncthreads();   // ep reusable next tile
    }
}

// ---------------------------------------------------------------------------
// Kernel 3: sum partials, mask, softmax per batch row
// ---------------------------------------------------------------------------
__global__ void softmax_kernel(const int* __restrict__ src_len,
                               float* __restrict__ out) {
    const int b = blockIdx.x;
    const int len = src_len[b];
    const int tid = threadIdx.x;
    __shared__ float sc[Ss];
    __shared__ float red[256];

    float lmax = -3.0e38f;
    for (int s = tid; s < Ss; s += 256) {
        float val = 0.f;
#pragma unroll
        for (int t = 0; t < NTILES; t++)
            val += g_partial[(size_t)t * Mtot + b * Ss + s];
        if (s >= len) val = -3.0e38f;
        sc[s] = val;
        lmax = fmaxf(lmax, val);
    }
    red[tid] = lmax;
    __syncthreads();
    for (int o = 128; o > 0; o >>= 1) {
        if (tid < o) red[tid] = fmaxf(red[tid], red[tid + o]);
        __syncthreads();
    }
    const float gmax = red[0];
    __syncthreads();

    float lsum = 0.f;
    for (int s = tid; s < Ss; s += 256) {
        float e = (s < len) ? __expf(sc[s] - gmax) : 0.f;
        sc[s] = e;
        lsum += e;
    }
    red[tid] = lsum;
    __syncthreads();
    for (int o = 128; o > 0; o >>= 1) {
        if (tid < o) red[tid] += red[tid + o];
        __syncthreads();
    }
    const float inv = 1.f / red[0];
    __syncthreads();
    for (int s = tid; s < Ss; s += 256) out[b * Ss + s] = sc[s] * inv;
}

// ---------------------------------------------------------------------------
extern "C" void kernel_launch(void* const* d_in, const int* in_sizes, int n_in,
                              void* d_out, int out_size) {
    const float* hidden  = (const float*)d_in[0];
    const float* enc     = (const float*)d_in[1];
    const float* W       = (const float*)d_in[2];
    const float* bias    = (const float*)d_in[3];
    const float* v       = (const float*)d_in[4];
    const int*   src_len = (const int*)d_in[5];
    float* out = (float*)d_out;

    int nsm = 148;
    cudaDeviceGetAttribute(&nsm, cudaDevAttrMultiProcessorCount, 0);
    const int grid = nsm * 2;

    cudaFuncSetAttribute(gemm_tanh_kernel,
                         cudaFuncAttributeMaxDynamicSharedMemorySize, SMEM_BYTES);

    fused_prep_kernel<<<ECONV_BLOCKS + WCONV_BLOCKS + PREP_BLOCKS, 256>>>(
        enc, W, hidden, bias);
    gemm_tanh_kernel<<<grid, 256, SMEM_BYTES>>>(v, grid);
    softmax_kernel<<<Bb, 256>>>(src_len, out);
}

// round 15
// speedup vs baseline: 1.0001x; 1.0001x over previous
#include <cuda_runtime.h>
#include <cuda_fp16.h>
#include <cstdint>

#define Dd 1024
#define Bb 32
#define Ss 2048
#define Mtot (Bb * Ss)          // 65536
#define M_TILE 128
#define N_TILE 128
#define K_TILE 64               // fp16 elems per stage
#define NSTG 3
#define NTILES (Dd / N_TILE)    // 8
#define NCHUNK (Dd / K_TILE)    // 16

#define ROW_BYTES 144           // 64 fp16 = 128B data + 16B pad (conflict-free)

#define OFF_HQ   0
#define OFF_V    512
#define OFF_BAR  1024           // full[0..2] at +0,8,16 ; empty[0..2] at +24,32,40
#define STAGE_BYTES (M_TILE * ROW_BYTES + N_TILE * ROW_BYTES)   // 36864
#define OFF_A(s) (2048 + (s) * STAGE_BYTES)
#define OFF_B(s) (OFF_A(s) + M_TILE * ROW_BYTES)
#define SMEM_BYTES (2048 + NSTG * STAGE_BYTES)                   // 112640

// fused prep kernel block ranges
#define ECONV_BLOCKS 8192
#define WCONV_BLOCKS 1024
#define PREP_BLOCKS  1024

__device__ float g_Hq[Bb * Dd];
__device__ __half g_Ehf[(size_t)Mtot * Dd];   // 128 MB
__device__ __half g_WhfT[Dd * Dd];            // 2 MB, [n][k]
__device__ float g_partial[NTILES * Mtot];    // 2 MB

__device__ __forceinline__ float tanh_fast(float x) {
    float y; asm("tanh.approx.f32 %0, %1;" : "=f"(y) : "f"(x)); return y;
}
__device__ __forceinline__ uint32_t pack_f16x2(float lo, float hi) {
    __half2 h = __floats2half2_rn(lo, hi);
    return *reinterpret_cast<uint32_t*>(&h);
}
__device__ __forceinline__ void mma_f16(float (&d)[4], const uint32_t (&a)[4],
                                        const uint32_t (&b)[2]) {
    asm volatile(
        "mma.sync.aligned.m16n8k16.row.col.f32.f16.f16.f32 "
        "{%0,%1,%2,%3}, {%4,%5,%6,%7}, {%8,%9}, {%0,%1,%2,%3};"
        : "+f"(d[0]), "+f"(d[1]), "+f"(d[2]), "+f"(d[3])
        : "r"(a[0]), "r"(a[1]), "r"(a[2]), "r"(a[3]), "r"(b[0]), "r"(b[1]));
}
__device__ __forceinline__ void ldmatrix_x4(uint32_t& r0, uint32_t& r1,
                                            uint32_t& r2, uint32_t& r3,
                                            uint32_t addr) {
    asm volatile("ldmatrix.sync.aligned.m8n8.x4.shared.b16 {%0,%1,%2,%3}, [%4];"
                 : "=r"(r0), "=r"(r1), "=r"(r2), "=r"(r3) : "r"(addr));
}
__device__ __forceinline__ void cp_async16(uint32_t dst, const void* src) {
    asm volatile("cp.async.cg.shared.global [%0], [%1], 16;"
                 :: "r"(dst), "l"(src) : "memory");
}
__device__ __forceinline__ uint32_t smem_u32(const void* p) {
    uint32_t a;
    asm("{ .reg .u64 t; cvta.to.shared.u64 t, %1; cvt.u32.u64 %0, t; }"
        : "=r"(a) : "l"(p));
    return a;
}

// ---- mbarrier primitives (sm_80+ portable subset) ----
#define MBARRIER_INIT(mbar, cnt) \
    asm volatile("mbarrier.init.shared.b64 [%0], %1;" \
        :: "r"((uint32_t)(mbar)), "r"((uint32_t)(cnt)) : "memory")
#define MBARRIER_ARRIVE(mbar) \
    asm volatile("mbarrier.arrive.shared.b64 _, [%0];" \
        :: "r"((uint32_t)(mbar)) : "memory")
#define CP_ASYNC_MBAR_ARRIVE(mbar) \
    asm volatile("cp.async.mbarrier.arrive.noinc.shared.b64 [%0];" \
        :: "r"((uint32_t)(mbar)) : "memory")

#define MBARRIER_WAIT_PARITY(mbar, parity) do { \
    uint32_t _m = (uint32_t)(mbar); uint32_t _p = (uint32_t)(parity); uint32_t _d; \
    asm volatile("{\n\t.reg .pred p;\n\t" \
        "mbarrier.try_wait.parity.shared.b64 p, [%1], %2;\n\t" \
        "selp.b32 %0, 1, 0, p;\n\t}" : "=r"(_d) : "r"(_m), "r"(_p) : "memory"); \
    if (!_d) { \
        asm volatile("{\n\t.reg .pred P1;\n\t" \
            "WL_%=:\n\t" \
            "mbarrier.try_wait.parity.shared.b64 P1, [%0], %1;\n\t" \
            "@P1 bra.uni WD_%=;\n\t" \
            "bra.uni WL_%=;\n\t" \
            "WD_%=:\n\t}" :: "r"(_m), "r"(_p) : "memory"); \
    } } while (0)

// ---------------------------------------------------------------------------
// Kernel 0 (fused prep): econv | wconvT | prep, partitioned by blockIdx.x.
// ---------------------------------------------------------------------------
__global__ void fused_prep_kernel(const float* __restrict__ E,
                                  const float* __restrict__ W,
                                  const float* __restrict__ hidden,
                                  const float* __restrict__ bias) {
    const int bid = blockIdx.x;
    const int t = threadIdx.x;

    if (bid < ECONV_BLOCKS) {
        // ---- E (fp32) -> g_Ehf (fp16), 32 elems/thread, streaming stores ----
        const size_t i = ((size_t)bid * 256 + t) * 32;
#pragma unroll
        for (int q = 0; q < 4; q++) {
            float4 x0 = __ldg(reinterpret_cast<const float4*>(E + i + q * 8));
            float4 x1 = __ldg(reinterpret_cast<const float4*>(E + i + q * 8 + 4));
            uint4 o;
            o.x = pack_f16x2(x0.x, x0.y);
            o.y = pack_f16x2(x0.z, x0.w);
            o.z = pack_f16x2(x1.x, x1.y);
            o.w = pack_f16x2(x1.z, x1.w);
            __stcs(reinterpret_cast<uint4*>(&g_Ehf[i + q * 8]), o);
        }
    } else if (bid < ECONV_BLOCKS + WCONV_BLOCKS) {
        __shared__ float tile[32][33];
        const int id = bid - ECONV_BLOCKS;
        const float* Wb = W + (size_t)Dd * Dd;
        const int kt = (id & 31) * 32;
        const int nt = (id >> 5) * 32;
        const int tx = t & 31, ty = t >> 5;
#pragma unroll
        for (int i = 0; i < 4; i++)
            tile[ty + 8 * i][tx] = Wb[(size_t)(kt + ty + 8 * i) * Dd + nt + tx];
        __syncthreads();
#pragma unroll
        for (int i = 0; i < 4; i++)
            g_WhfT[(size_t)(nt + ty + 8 * i) * Dd + kt + tx] =
                __float2half_rn(tile[tx][ty + 8 * i]);
    } else {
        __shared__ float h[Dd];
        __shared__ float red[256];
        const int id = bid - ECONV_BLOCKS - WCONV_BLOCKS;
        const int n0 = (id & 31) * 32;
        const int b = id >> 5;
        {
            float4 v4 = *reinterpret_cast<const float4*>(hidden + b * Dd + t * 4);
            h[t * 4 + 0] = v4.x; h[t * 4 + 1] = v4.y;
            h[t * 4 + 2] = v4.z; h[t * 4 + 3] = v4.w;
        }
        __syncthreads();
        const int n = n0 + (t & 31);
        const int kbeg = (t >> 5) * 128;
        float acc = 0.f;
#pragma unroll 8
        for (int k = kbeg; k < kbeg + 128; k++)
            acc = fmaf(h[k], W[(size_t)k * Dd + n], acc);
        red[t] = acc;
        __syncthreads();
        if (t < 32) {
            float s = bias[n0 + t];
#pragma unroll
            for (int j = 0; j < 8; j++) s += red[j * 32 + t];
            g_Hq[b * Dd + n0 + t] = s;
        }
    }
}

// ---------------------------------------------------------------------------
// Kernel 2: fp16 GEMM with mbarrier producer/consumer pipeline (no per-ktile
// __syncthreads). 8 warps of 64x32, 2 CTA/SM. grid (8, 512), block 256
// (identical to round-13 best)
// ---------------------------------------------------------------------------
__global__ __launch_bounds__(256, 2)
void gemm_tanh_kernel(const float* __restrict__ v) {
    extern __shared__ __align__(1024) char smem[];
    const uint32_t sb = smem_u32(smem);

    const int tid = threadIdx.x;
    const int wid = tid >> 5;
    const int lane = tid & 31;
    const int g = lane >> 2;
    const int tig = lane & 3;
    const int warp_m = wid & 1;        // 2 warps along M (64 rows each)
    const int warp_n = wid >> 1;       // 4 warps along N (32 cols each)

    const int n0 = blockIdx.x * N_TILE;
    const int m0 = blockIdx.y * M_TILE;
    const int b = blockIdx.y >> 4;

    const uint32_t FULL  = sb + OFF_BAR;        // +8*s
    const uint32_t EMPTY = sb + OFF_BAR + 24;   // +8*s

    if (tid == 0) {
#pragma unroll
        for (int s = 0; s < NSTG; s++) {
            MBARRIER_INIT(FULL + 8 * s, 256);   // one completion-arrive per thread
            MBARRIER_INIT(EMPTY + 8 * s, 8);    // one arrive per warp
        }
    }

    float* hq_s = reinterpret_cast<float*>(smem + OFF_HQ);
    float* v_s  = reinterpret_cast<float*>(smem + OFF_V);
    if (tid < N_TILE) {
        hq_s[tid] = g_Hq[b * Dd + n0 + tid];
        v_s[tid]  = v[n0 + tid];
    }
    __syncthreads();   // mbarrier init + hq/v visible

    uint32_t aoff[4], boff[2];
#pragma unroll
    for (int mf = 0; mf < 4; mf++) {
        int row = warp_m * 64 + mf * 16 + (lane & 7) + ((lane >> 3) & 1) * 8;
        aoff[mf] = row * ROW_BYTES + ((lane >> 4) & 1) * 16;
    }
#pragma unroll
    for (int np = 0; np < 2; np++) {
        int row = warp_n * 32 + np * 16 + (lane & 7) + ((lane >> 4) & 1) * 8;
        boff[np] = row * ROW_BYTES + ((lane >> 3) & 1) * 16;
    }

    auto issue_stage = [&](int j) {
        const int kt = j * K_TILE;
        const int s = j % NSTG;
        const uint32_t abase = sb + OFF_A(s);
        const uint32_t bbase = sb + OFF_B(s);
#pragma unroll
        for (int p = 0; p < 4; p++) {
            int id = tid + p * 256;               // 0..1023
            int row = id >> 3, ch = id & 7;
            cp_async16(abase + row * ROW_BYTES + ch * 16,
                       &g_Ehf[(size_t)(m0 + row) * Dd + kt + ch * 8]);
        }
#pragma unroll
        for (int p = 0; p < 4; p++) {
            int id = tid + p * 256;
            int row = id >> 3, ch = id & 7;
            cp_async16(bbase + row * ROW_BYTES + ch * 16,
                       &g_WhfT[(size_t)(n0 + row) * Dd + kt + ch * 8]);
        }
        CP_ASYNC_MBAR_ARRIVE(FULL + 8 * s);       // signal on completion
    };

    issue_stage(0);
    issue_stage(1);

    float acc[4][4][4];
#pragma unroll
    for (int mf = 0; mf < 4; mf++)
#pragma unroll
        for (int nf = 0; nf < 4; nf++)
#pragma unroll
            for (int i = 0; i < 4; i++) acc[mf][nf][i] = 0.f;

#pragma unroll 1
    for (int i = 0; i < NCHUNK; i++) {
        const int s = i % NSTG;
        // consumer: wait for stage i data (all 256 threads' copies done)
        MBARRIER_WAIT_PARITY(FULL + 8 * s, (i / NSTG) & 1);

        const uint32_t As = sb + OFF_A(s);
        const uint32_t Bs = sb + OFF_B(s);
#pragma unroll
        for (int kk = 0; kk < 4; kk++) {          // 4 x k16 steps
            const int kb = kk * 32;
            uint32_t afrag[4][4], bfrag[4][2];
#pragma unroll
            for (int mf = 0; mf < 4; mf++)
                ldmatrix_x4(afrag[mf][0], afrag[mf][1], afrag[mf][2], afrag[mf][3],
                            As + aoff[mf] + kb);
#pragma unroll
            for (int np = 0; np < 2; np++)
                ldmatrix_x4(bfrag[2 * np][0], bfrag[2 * np][1],
                            bfrag[2 * np + 1][0], bfrag[2 * np + 1][1],
                            Bs + boff[np] + kb);
#pragma unroll
            for (int mf = 0; mf < 4; mf++)
#pragma unroll
                for (int nf = 0; nf < 4; nf++)
                    mma_f16(acc[mf][nf], afrag[mf], bfrag[nf]);
        }
        // this warp is done reading stage s
        if (lane == 0) MBARRIER_ARRIVE(EMPTY + 8 * s);

        // producer: refill stage i+2 once every warp has released it
        const int j = i + 2;
        if (j < NCHUNK) {
            const int s2 = j % NSTG;
            if (j >= NSTG)
                MBARRIER_WAIT_PARITY(EMPTY + 8 * s2, ((j / NSTG) - 1) & 1);
            issue_stage(j);
        }
    }
    __syncthreads();

    // ---- epilogue: tanh + v-weighted row reduction ----
    float hq[8], vv[8];
#pragma unroll
    for (int nf = 0; nf < 4; nf++)
#pragma unroll
        for (int j = 0; j < 2; j++) {
            const int c = warp_n * 32 + nf * 8 + 2 * tig + j;
            hq[nf * 2 + j] = hq_s[c];
            vv[nf * 2 + j] = v_s[c];
        }

    float psum[8];
#pragma unroll
    for (int r = 0; r < 8; r++) psum[r] = 0.f;
#pragma unroll
    for (int mf = 0; mf < 4; mf++)
#pragma unroll
        for (int nf = 0; nf < 4; nf++)
#pragma unroll
            for (int i = 0; i < 4; i++) {
                const int half = i >> 1;
                const int j = i & 1;
                float e = tanh_fast(acc[mf][nf][i] + hq[nf * 2 + j]);
                psum[mf * 2 + half] = fmaf(e, vv[nf * 2 + j], psum[mf * 2 + half]);
            }
#pragma unroll
    for (int r = 0; r < 8; r++) {
        psum[r] += __shfl_xor_sync(0xffffffffu, psum[r], 1);
        psum[r] += __shfl_xor_sync(0xffffffffu, psum[r], 2);
    }

    float* sums = reinterpret_cast<float*>(smem + OFF_A(0));  // 128 x 4 floats
    if (tig == 0) {
#pragma unroll
        for (int r = 0; r < 8; r++) {
            const int mf = r >> 1, half = r & 1;
            const int lrow = warp_m * 64 + mf * 16 + half * 8 + g;
            sums[lrow * 4 + warp_n] = psum[r];
        }
    }
    __syncthreads();
    if (tid < M_TILE) {
        float t = sums[tid * 4] + sums[tid * 4 + 1] +
                  sums[tid * 4 + 2] + sums[tid * 4 + 3];
        g_partial[(size_t)blockIdx.x * Mtot + m0 + tid] = t;
    }
}

// ---------------------------------------------------------------------------
// Kernel 3: sum partials, mask, softmax per batch row (1024 threads)
// ---------------------------------------------------------------------------
__global__ void softmax_kernel(const int* __restrict__ src_len,
                               float* __restrict__ out) {
    const int b = blockIdx.x;
    const int len = src_len[b];
    const int tid = threadIdx.x;
    __shared__ float sc[Ss];
    __shared__ float red[1024];

    float lmax = -3.0e38f;
    for (int s = tid; s < Ss; s += 1024) {
        float val = 0.f;
#pragma unroll
        for (int t = 0; t < NTILES; t++)
            val += g_partial[(size_t)t * Mtot + b * Ss + s];
        if (s >= len) val = -3.0e38f;
        sc[s] = val;
        lmax = fmaxf(lmax, val);
    }
    red[tid] = lmax;
    __syncthreads();
    for (int o = 512; o > 0; o >>= 1) {
        if (tid < o) red[tid] = fmaxf(red[tid], red[tid + o]);
        __syncthreads();
    }
    const float gmax = red[0];
    __syncthreads();

    float lsum = 0.f;
    for (int s = tid; s < Ss; s += 1024) {
        float e = (s < len) ? __expf(sc[s] - gmax) : 0.f;
        sc[s] = e;
        lsum += e;
    }
    red[tid] = lsum;
    __syncthreads();
    for (int o = 512; o > 0; o >>= 1) {
        if (tid < o) red[tid] += red[tid + o];
        __syncthreads();
    }
    const float inv = 1.f / red[0];
    __syncthreads();
    for (int s = tid; s < Ss; s += 1024) out[b * Ss + s] = sc[s] * inv;
}

// ---------------------------------------------------------------------------
extern "C" void kernel_launch(void* const* d_in, const int* in_sizes, int n_in,
                              void* d_out, int out_size) {
    const float* hidden  = (const float*)d_in[0];
    const float* enc     = (const float*)d_in[1];
    const float* W       = (const float*)d_in[2];
    const float* bias    = (const float*)d_in[3];
    const float* v       = (const float*)d_in[4];
    const int*   src_len = (const int*)d_in[5];
    float* out = (float*)d_out;

    cudaFuncSetAttribute(gemm_tanh_kernel,
                         cudaFuncAttributeMaxDynamicSharedMemorySize, SMEM_BYTES);

    fused_prep_kernel<<<ECONV_BLOCKS + WCONV_BLOCKS + PREP_BLOCKS, 256>>>(
        enc, W, hidden, bias);
    gemm_tanh_kernel<<<dim3(NTILES, Mtot / M_TILE), 256, SMEM_BYTES>>>(v);
    softmax_kernel<<<Bb, 1024>>>(src_len, out);
}

// round 16
// speedup vs baseline: 1.0800x; 1.0799x over previous
#include <cuda_runtime.h>
#include <cuda_fp16.h>
#include <cstdint>

#define Dd 1024
#define Bb 32
#define Ss 2048
#define Mtot (Bb * Ss)          // 65536
#define M_TILE 128
#define N_TILE 128
#define K_TILE 64               // fp16 elems per stage
#define NSTG 3
#define NTILES (Dd / N_TILE)    // 8
#define NCHUNK (Dd / K_TILE)    // 16

#define ROW_BYTES 144           // 64 fp16 = 128B data + 16B pad (conflict-free)

#define OFF_HQ   0
#define OFF_V    512
#define OFF_BAR  1024           // full[0..2] at +0,8,16 ; empty[0..2] at +24,32,40
#define STAGE_BYTES (M_TILE * ROW_BYTES + N_TILE * ROW_BYTES)   // 36864
#define OFF_A(s) (2048 + (s) * STAGE_BYTES)
#define OFF_B(s) (OFF_A(s) + M_TILE * ROW_BYTES)
#define SMEM_BYTES (2048 + NSTG * STAGE_BYTES)                   // 112640

// fused prep kernel block ranges (R13-proven: 16 elems/thread econv)
#define ECONV_BLOCKS 16384
#define WCONV_BLOCKS 1024
#define PREP_BLOCKS  1024

__device__ float g_Hq[Bb * Dd];
__device__ __half g_Ehf[(size_t)Mtot * Dd];   // 128 MB
__device__ __half g_WhfT[Dd * Dd];            // 2 MB, [n][k]
__device__ float g_partial[NTILES * Mtot];    // 2 MB

__device__ __forceinline__ float tanh_fast(float x) {
    float y; asm("tanh.approx.f32 %0, %1;" : "=f"(y) : "f"(x)); return y;
}
__device__ __forceinline__ uint32_t pack_f16x2(float lo, float hi) {
    __half2 h = __floats2half2_rn(lo, hi);
    return *reinterpret_cast<uint32_t*>(&h);
}
__device__ __forceinline__ void mma_f16(float (&d)[4], const uint32_t (&a)[4],
                                        const uint32_t (&b)[2]) {
    asm volatile(
        "mma.sync.aligned.m16n8k16.row.col.f32.f16.f16.f32 "
        "{%0,%1,%2,%3}, {%4,%5,%6,%7}, {%8,%9}, {%0,%1,%2,%3};"
        : "+f"(d[0]), "+f"(d[1]), "+f"(d[2]), "+f"(d[3])
        : "r"(a[0]), "r"(a[1]), "r"(a[2]), "r"(a[3]), "r"(b[0]), "r"(b[1]));
}
__device__ __forceinline__ void ldmatrix_x4(uint32_t& r0, uint32_t& r1,
                                            uint32_t& r2, uint32_t& r3,
                                            uint32_t addr) {
    asm volatile("ldmatrix.sync.aligned.m8n8.x4.shared.b16 {%0,%1,%2,%3}, [%4];"
                 : "=r"(r0), "=r"(r1), "=r"(r2), "=r"(r3) : "r"(addr));
}
__device__ __forceinline__ void cp_async16(uint32_t dst, const void* src) {
    asm volatile("cp.async.cg.shared.global [%0], [%1], 16;"
                 :: "r"(dst), "l"(src) : "memory");
}
__device__ __forceinline__ uint32_t smem_u32(const void* p) {
    uint32_t a;
    asm("{ .reg .u64 t; cvta.to.shared.u64 t, %1; cvt.u32.u64 %0, t; }"
        : "=r"(a) : "l"(p));
    return a;
}

// ---- mbarrier primitives (sm_80+ portable subset) ----
#define MBARRIER_INIT(mbar, cnt) \
    asm volatile("mbarrier.init.shared.b64 [%0], %1;" \
        :: "r"((uint32_t)(mbar)), "r"((uint32_t)(cnt)) : "memory")
#define MBARRIER_ARRIVE(mbar) \
    asm volatile("mbarrier.arrive.shared.b64 _, [%0];" \
        :: "r"((uint32_t)(mbar)) : "memory")
#define CP_ASYNC_MBAR_ARRIVE(mbar) \
    asm volatile("cp.async.mbarrier.arrive.noinc.shared.b64 [%0];" \
        :: "r"((uint32_t)(mbar)) : "memory")

#define MBARRIER_WAIT_PARITY(mbar, parity) do { \
    uint32_t _m = (uint32_t)(mbar); uint32_t _p = (uint32_t)(parity); uint32_t _d; \
    asm volatile("{\n\t.reg .pred p;\n\t" \
        "mbarrier.try_wait.parity.shared.b64 p, [%1], %2;\n\t" \
        "selp.b32 %0, 1, 0, p;\n\t}" : "=r"(_d) : "r"(_m), "r"(_p) : "memory"); \
    if (!_d) { \
        asm volatile("{\n\t.reg .pred P1;\n\t" \
            "WL_%=:\n\t" \
            "mbarrier.try_wait.parity.shared.b64 P1, [%0], %1;\n\t" \
            "@P1 bra.uni WD_%=;\n\t" \
            "bra.uni WL_%=;\n\t" \
            "WD_%=:\n\t}" :: "r"(_m), "r"(_p) : "memory"); \
    } } while (0)

// ---------------------------------------------------------------------------
// Kernel 0 (fused prep): econv | wconvT | prep, partitioned by blockIdx.x.
// (byte-identical to round-13 best)
// ---------------------------------------------------------------------------
__global__ void fused_prep_kernel(const float* __restrict__ E,
                                  const float* __restrict__ W,
                                  const float* __restrict__ hidden,
                                  const float* __restrict__ bias) {
    const int bid = blockIdx.x;
    const int t = threadIdx.x;

    if (bid < ECONV_BLOCKS) {
        const size_t i = ((size_t)bid * 256 + t) * 16;
#pragma unroll
        for (int q = 0; q < 2; q++) {
            float4 x0 = __ldg(reinterpret_cast<const float4*>(E + i + q * 8));
            float4 x1 = __ldg(reinterpret_cast<const float4*>(E + i + q * 8 + 4));
            uint4 o;
            o.x = pack_f16x2(x0.x, x0.y);
            o.y = pack_f16x2(x0.z, x0.w);
            o.z = pack_f16x2(x1.x, x1.y);
            o.w = pack_f16x2(x1.z, x1.w);
            __stcs(reinterpret_cast<uint4*>(&g_Ehf[i + q * 8]), o);
        }
    } else if (bid < ECONV_BLOCKS + WCONV_BLOCKS) {
        __shared__ float tile[32][33];
        const int id = bid - ECONV_BLOCKS;
        const float* Wb = W + (size_t)Dd * Dd;
        const int kt = (id & 31) * 32;
        const int nt = (id >> 5) * 32;
        const int tx = t & 31, ty = t >> 5;
#pragma unroll
        for (int i = 0; i < 4; i++)
            tile[ty + 8 * i][tx] = Wb[(size_t)(kt + ty + 8 * i) * Dd + nt + tx];
        __syncthreads();
#pragma unroll
        for (int i = 0; i < 4; i++)
            g_WhfT[(size_t)(nt + ty + 8 * i) * Dd + kt + tx] =
                __float2half_rn(tile[tx][ty + 8 * i]);
    } else {
        __shared__ float h[Dd];
        __shared__ float red[256];
        const int id = bid - ECONV_BLOCKS - WCONV_BLOCKS;
        const int n0 = (id & 31) * 32;
        const int b = id >> 5;
        {
            float4 v4 = *reinterpret_cast<const float4*>(hidden + b * Dd + t * 4);
            h[t * 4 + 0] = v4.x; h[t * 4 + 1] = v4.y;
            h[t * 4 + 2] = v4.z; h[t * 4 + 3] = v4.w;
        }
        __syncthreads();
        const int n = n0 + (t & 31);
        const int kbeg = (t >> 5) * 128;
        float acc = 0.f;
#pragma unroll 8
        for (int k = kbeg; k < kbeg + 128; k++)
            acc = fmaf(h[k], W[(size_t)k * Dd + n], acc);
        red[t] = acc;
        __syncthreads();
        if (t < 32) {
            float s = bias[n0 + t];
#pragma unroll
            for (int j = 0; j < 8; j++) s += red[j * 32 + t];
            g_Hq[b * Dd + n0 + t] = s;
        }
    }
}

// ---------------------------------------------------------------------------
// Kernel 2: fp16 GEMM with mbarrier producer/consumer pipeline (no per-ktile
// __syncthreads). 8 warps of 64x32, 2 CTA/SM. grid (8, 512), block 256
// (byte-identical to round-13 best)
// ---------------------------------------------------------------------------
__global__ __launch_bounds__(256, 2)
void gemm_tanh_kernel(const float* __restrict__ v) {
    extern __shared__ __align__(1024) char smem[];
    const uint32_t sb = smem_u32(smem);

    const int tid = threadIdx.x;
    const int wid = tid >> 5;
    const int lane = tid & 31;
    const int g = lane >> 2;
    const int tig = lane & 3;
    const int warp_m = wid & 1;        // 2 warps along M (64 rows each)
    const int warp_n = wid >> 1;       // 4 warps along N (32 cols each)

    const int n0 = blockIdx.x * N_TILE;
    const int m0 = blockIdx.y * M_TILE;
    const int b = blockIdx.y >> 4;

    const uint32_t FULL  = sb + OFF_BAR;        // +8*s
    const uint32_t EMPTY = sb + OFF_BAR + 24;   // +8*s

    if (tid == 0) {
#pragma unroll
        for (int s = 0; s < NSTG; s++) {
            MBARRIER_INIT(FULL + 8 * s, 256);   // one completion-arrive per thread
            MBARRIER_INIT(EMPTY + 8 * s, 8);    // one arrive per warp
        }
    }

    float* hq_s = reinterpret_cast<float*>(smem + OFF_HQ);
    float* v_s  = reinterpret_cast<float*>(smem + OFF_V);
    if (tid < N_TILE) {
        hq_s[tid] = g_Hq[b * Dd + n0 + tid];
        v_s[tid]  = v[n0 + tid];
    }
    __syncthreads();   // mbarrier init + hq/v visible

    uint32_t aoff[4], boff[2];
#pragma unroll
    for (int mf = 0; mf < 4; mf++) {
        int row = warp_m * 64 + mf * 16 + (lane & 7) + ((lane >> 3) & 1) * 8;
        aoff[mf] = row * ROW_BYTES + ((lane >> 4) & 1) * 16;
    }
#pragma unroll
    for (int np = 0; np < 2; np++) {
        int row = warp_n * 32 + np * 16 + (lane & 7) + ((lane >> 4) & 1) * 8;
        boff[np] = row * ROW_BYTES + ((lane >> 3) & 1) * 16;
    }

    auto issue_stage = [&](int j) {
        const int kt = j * K_TILE;
        const int s = j % NSTG;
        const uint32_t abase = sb + OFF_A(s);
        const uint32_t bbase = sb + OFF_B(s);
#pragma unroll
        for (int p = 0; p < 4; p++) {
            int id = tid + p * 256;               // 0..1023
            int row = id >> 3, ch = id & 7;
            cp_async16(abase + row * ROW_BYTES + ch * 16,
                       &g_Ehf[(size_t)(m0 + row) * Dd + kt + ch * 8]);
        }
#pragma unroll
        for (int p = 0; p < 4; p++) {
            int id = tid + p * 256;
            int row = id >> 3, ch = id & 7;
            cp_async16(bbase + row * ROW_BYTES + ch * 16,
                       &g_WhfT[(size_t)(n0 + row) * Dd + kt + ch * 8]);
        }
        CP_ASYNC_MBAR_ARRIVE(FULL + 8 * s);       // signal on completion
    };

    issue_stage(0);
    issue_stage(1);

    float acc[4][4][4];
#pragma unroll
    for (int mf = 0; mf < 4; mf++)
#pragma unroll
        for (int nf = 0; nf < 4; nf++)
#pragma unroll
            for (int i = 0; i < 4; i++) acc[mf][nf][i] = 0.f;

#pragma unroll 1
    for (int i = 0; i < NCHUNK; i++) {
        const int s = i % NSTG;
        // consumer: wait for stage i data (all 256 threads' copies done)
        MBARRIER_WAIT_PARITY(FULL + 8 * s, (i / NSTG) & 1);

        const uint32_t As = sb + OFF_A(s);
        const uint32_t Bs = sb + OFF_B(s);
#pragma unroll
        for (int kk = 0; kk < 4; kk++) {          // 4 x k16 steps
            const int kb = kk * 32;
            uint32_t afrag[4][4], bfrag[4][2];
#pragma unroll
            for (int mf = 0; mf < 4; mf++)
                ldmatrix_x4(afrag[mf][0], afrag[mf][1], afrag[mf][2], afrag[mf][3],
                            As + aoff[mf] + kb);
#pragma unroll
            for (int np = 0; np < 2; np++)
                ldmatrix_x4(bfrag[2 * np][0], bfrag[2 * np][1],
                            bfrag[2 * np + 1][0], bfrag[2 * np + 1][1],
                            Bs + boff[np] + kb);
#pragma unroll
            for (int mf = 0; mf < 4; mf++)
#pragma unroll
                for (int nf = 0; nf < 4; nf++)
                    mma_f16(acc[mf][nf], afrag[mf], bfrag[nf]);
        }
        // this warp is done reading stage s
        if (lane == 0) MBARRIER_ARRIVE(EMPTY + 8 * s);

        // producer: refill stage i+2 once every warp has released it
        const int j = i + 2;
        if (j < NCHUNK) {
            const int s2 = j % NSTG;
            if (j >= NSTG)
                MBARRIER_WAIT_PARITY(EMPTY + 8 * s2, ((j / NSTG) - 1) & 1);
            issue_stage(j);
        }
    }
    __syncthreads();

    // ---- epilogue: tanh + v-weighted row reduction ----
    float hq[8], vv[8];
#pragma unroll
    for (int nf = 0; nf < 4; nf++)
#pragma unroll
        for (int j = 0; j < 2; j++) {
            const int c = warp_n * 32 + nf * 8 + 2 * tig + j;
            hq[nf * 2 + j] = hq_s[c];
            vv[nf * 2 + j] = v_s[c];
        }

    float psum[8];
#pragma unroll
    for (int r = 0; r < 8; r++) psum[r] = 0.f;
#pragma unroll
    for (int mf = 0; mf < 4; mf++)
#pragma unroll
        for (int nf = 0; nf < 4; nf++)
#pragma unroll
            for (int i = 0; i < 4; i++) {
                const int half = i >> 1;
                const int j = i & 1;
                float e = tanh_fast(acc[mf][nf][i] + hq[nf * 2 + j]);
                psum[mf * 2 + half] = fmaf(e, vv[nf * 2 + j], psum[mf * 2 + half]);
            }
#pragma unroll
    for (int r = 0; r < 8; r++) {
        psum[r] += __shfl_xor_sync(0xffffffffu, psum[r], 1);
        psum[r] += __shfl_xor_sync(0xffffffffu, psum[r], 2);
    }

    float* sums = reinterpret_cast<float*>(smem + OFF_A(0));  // 128 x 4 floats
    if (tig == 0) {
#pragma unroll
        for (int r = 0; r < 8; r++) {
            const int mf = r >> 1, half = r & 1;
            const int lrow = warp_m * 64 + mf * 16 + half * 8 + g;
            sums[lrow * 4 + warp_n] = psum[r];
        }
    }
    __syncthreads();
    if (tid < M_TILE) {
        float t = sums[tid * 4] + sums[tid * 4 + 1] +
                  sums[tid * 4 + 2] + sums[tid * 4 + 3];
        g_partial[(size_t)blockIdx.x * Mtot + m0 + tid] = t;
    }
}

// ---------------------------------------------------------------------------
// Kernel 3: sum partials, mask, softmax per batch row (1024 threads)
// ---------------------------------------------------------------------------
__global__ void softmax_kernel(const int* __restrict__ src_len,
                               float* __restrict__ out) {
    const int b = blockIdx.x;
    const int len = src_len[b];
    const int tid = threadIdx.x;
    __shared__ float sc[Ss];
    __shared__ float red[1024];

    float lmax = -3.0e38f;
    for (int s = tid; s < Ss; s += 1024) {
        float val = 0.f;
#pragma unroll
        for (int t = 0; t < NTILES; t++)
            val += g_partial[(size_t)t * Mtot + b * Ss + s];
        if (s >= len) val = -3.0e38f;
        sc[s] = val;
        lmax = fmaxf(lmax, val);
    }
    red[tid] = lmax;
    __syncthreads();
    for (int o = 512; o > 0; o >>= 1) {
        if (tid < o) red[tid] = fmaxf(red[tid], red[tid + o]);
        __syncthreads();
    }
    const float gmax = red[0];
    __syncthreads();

    float lsum = 0.f;
    for (int s = tid; s < Ss; s += 1024) {
        float e = (s < len) ? __expf(sc[s] - gmax) : 0.f;
        sc[s] = e;
        lsum += e;
    }
    red[tid] = lsum;
    __syncthreads();
    for (int o = 512; o > 0; o >>= 1) {
        if (tid < o) red[tid] += red[tid + o];
        __syncthreads();
    }
    const float inv = 1.f / red[0];
    __syncthreads();
    for (int s = tid; s < Ss; s += 1024) out[b * Ss + s] = sc[s] * inv;
}

// ---------------------------------------------------------------------------
extern "C" void kernel_launch(void* const* d_in, const int* in_sizes, int n_in,
                              void* d_out, int out_size) {
    const float* hidden  = (const float*)d_in[0];
    const float* enc     = (const float*)d_in[1];
    const float* W       = (const float*)d_in[2];
    const float* bias    = (const float*)d_in[3];
    const float* v       = (const float*)d_in[4];
    const int*   src_len = (const int*)d_in[5];
    float* out = (float*)d_out;

    cudaFuncSetAttribute(gemm_tanh_kernel,
                         cudaFuncAttributeMaxDynamicSharedMemorySize, SMEM_BYTES);

    fused_prep_kernel<<<ECONV_BLOCKS + WCONV_BLOCKS + PREP_BLOCKS, 256>>>(
        enc, W, hidden, bias);
    gemm_tanh_kernel<<<dim3(NTILES, Mtot / M_TILE), 256, SMEM_BYTES>>>(v);
    softmax_kernel<<<Bb, 1024>>>(src_len, out);
}